// round 1
// baseline (speedup 1.0000x reference)
#include <cuda_runtime.h>

// Problem constants (fixed shapes from reference)
#define BB  8
#define CC  512
#define HWD 1024
#define RR  8192   // BB*HWD

// Scratch (device globals — no runtime allocation allowed)
__device__ float g_q[RR * CC];
__device__ float g_k[RR * CC];
__device__ float g_pmax[RR * BB];   // per-query, per-image max score
__device__ float g_w[BB * HWD];     // softmax gate weights

// ----------------------------------------------------------------------------
// Kernel 1: q/k projection.
//   out[row, co] = sum_ci xf[row,ci] * W[co,ci] + bias[co]
//   xf[row, ci] = x[b, ci, p],  row = b*HWD + p
// 128x128 tile, BK=16, 256 threads, 8x8 per thread.
// ----------------------------------------------------------------------------
__global__ __launch_bounds__(256) void proj_kernel(
    const float* __restrict__ x, const float* __restrict__ W,
    const float* __restrict__ bias, int dst)
{
    float* out = dst ? g_k : g_q;
    __shared__ float As[16][128];   // As[kk][r]  = xf tile
    __shared__ float Bs[16][128];   // Bs[kk][co] = W tile

    const int r0  = blockIdx.x * 128;
    const int co0 = blockIdx.y * 128;
    const int b   = r0 / HWD;
    const int p0  = r0 % HWD;
    const int t   = threadIdx.x;
    const int tx  = t & 15;
    const int ty  = t >> 4;

    float acc[8][8];
    #pragma unroll
    for (int i = 0; i < 8; i++)
        #pragma unroll
        for (int j = 0; j < 8; j++) acc[i][j] = 0.f;

    const float* xb = x + (size_t)b * CC * HWD;

    for (int k0 = 0; k0 < CC; k0 += 16) {
        // A: contiguous along p. 512 float4s / 256 threads = 2 each.
        #pragma unroll
        for (int u = 0; u < 2; u++) {
            int f  = t + u * 256;
            int kk = f >> 5;
            int r4 = (f & 31) << 2;
            float4 v = *(const float4*)(xb + (size_t)(k0 + kk) * HWD + p0 + r4);
            *(float4*)(&As[kk][r4]) = v;
        }
        // B: W row-major [co][ci]; float4 along ci, scatter-store transposed.
        #pragma unroll
        for (int u = 0; u < 2; u++) {
            int f  = t + u * 256;
            int co = f >> 2;
            int kq = (f & 3) << 2;
            float4 v = *(const float4*)(W + (size_t)(co0 + co) * CC + k0 + kq);
            Bs[kq + 0][co] = v.x; Bs[kq + 1][co] = v.y;
            Bs[kq + 2][co] = v.z; Bs[kq + 3][co] = v.w;
        }
        __syncthreads();
        #pragma unroll
        for (int kk = 0; kk < 16; kk++) {
            float a[8], bf[8];
            #pragma unroll
            for (int i = 0; i < 8; i++) a[i]  = As[kk][ty * 8 + i];
            #pragma unroll
            for (int j = 0; j < 8; j++) bf[j] = Bs[kk][tx * 8 + j];
            #pragma unroll
            for (int i = 0; i < 8; i++)
                #pragma unroll
                for (int j = 0; j < 8; j++)
                    acc[i][j] += a[i] * bf[j];
        }
        __syncthreads();
    }

    #pragma unroll
    for (int i = 0; i < 8; i++) {
        int row = r0 + ty * 8 + i;
        #pragma unroll
        for (int j = 0; j < 8; j++) {
            int co = co0 + tx * 8 + j;
            out[(size_t)row * CC + co] = acc[i][j] + bias[co];
        }
    }
}

// ----------------------------------------------------------------------------
// Kernel 2: fused scores + per-image max.
//   For 128 queries (blockIdx.x) vs one image's 1024 keys (blockIdx.y):
//   stream key chunks of 128, full K=512 dot, track running per-query max.
//   Never materializes the 8192x8192 scores matrix.
// ----------------------------------------------------------------------------
__global__ __launch_bounds__(256) void scores_kernel()
{
    __shared__ float As[16][128];   // As[kk][r] = Q[(q0+r), k0+kk]
    __shared__ float Bs[16][128];   // Bs[kk][c] = K[(kb+kc+c), k0+kk]
    __shared__ float red[128][17];

    const int q0 = blockIdx.x * 128;
    const int kb = blockIdx.y * HWD;
    const int t  = threadIdx.x;
    const int tx = t & 15;
    const int ty = t >> 4;

    float qmax[8];
    #pragma unroll
    for (int i = 0; i < 8; i++) qmax[i] = -1e30f;

    for (int kc = 0; kc < HWD; kc += 128) {
        float acc[8][8];
        #pragma unroll
        for (int i = 0; i < 8; i++)
            #pragma unroll
            for (int j = 0; j < 8; j++) acc[i][j] = 0.f;

        for (int k0 = 0; k0 < CC; k0 += 16) {
            #pragma unroll
            for (int u = 0; u < 2; u++) {
                int f  = t + u * 256;
                int r  = f >> 2;
                int kq = (f & 3) << 2;
                float4 v = *(const float4*)(g_q + (size_t)(q0 + r) * CC + k0 + kq);
                As[kq + 0][r] = v.x; As[kq + 1][r] = v.y;
                As[kq + 2][r] = v.z; As[kq + 3][r] = v.w;
            }
            #pragma unroll
            for (int u = 0; u < 2; u++) {
                int f  = t + u * 256;
                int c  = f >> 2;
                int kq = (f & 3) << 2;
                float4 v = *(const float4*)(g_k + (size_t)(kb + kc + c) * CC + k0 + kq);
                Bs[kq + 0][c] = v.x; Bs[kq + 1][c] = v.y;
                Bs[kq + 2][c] = v.z; Bs[kq + 3][c] = v.w;
            }
            __syncthreads();
            #pragma unroll
            for (int kk = 0; kk < 16; kk++) {
                float a[8], bf[8];
                #pragma unroll
                for (int i = 0; i < 8; i++) a[i]  = As[kk][ty * 8 + i];
                #pragma unroll
                for (int j = 0; j < 8; j++) bf[j] = Bs[kk][tx * 8 + j];
                #pragma unroll
                for (int i = 0; i < 8; i++)
                    #pragma unroll
                    for (int j = 0; j < 8; j++)
                        acc[i][j] += a[i] * bf[j];
            }
            __syncthreads();
        }
        #pragma unroll
        for (int i = 0; i < 8; i++)
            #pragma unroll
            for (int j = 0; j < 8; j++)
                qmax[i] = fmaxf(qmax[i], acc[i][j]);
    }

    // reduce qmax across the 16 column-thread groups
    #pragma unroll
    for (int i = 0; i < 8; i++) red[ty * 8 + i][tx] = qmax[i];
    __syncthreads();
    if (t < 128) {
        float m = red[t][0];
        #pragma unroll
        for (int j = 1; j < 16; j++) m = fmaxf(m, red[t][j]);
        g_pmax[(size_t)(q0 + t) * BB + blockIdx.y] = m;
    }
}

// ----------------------------------------------------------------------------
// Kernel 3: logits = mean-over-images(pmax) * (1/sqrt(C)); softmax per batch.
// ----------------------------------------------------------------------------
__global__ __launch_bounds__(256) void softmax_kernel()
{
    const int b = blockIdx.x;
    const int t = threadIdx.x;
    __shared__ float sm[256];
    __shared__ float logits[HWD];
    const float scale = 1.0f / sqrtf((float)CC);

    float lmax = -1e30f;
    for (int p = t; p < HWD; p += 256) {
        float s = 0.f;
        #pragma unroll
        for (int img = 0; img < BB; img++)
            s += g_pmax[(size_t)(b * HWD + p) * BB + img];
        float lg = s * (1.0f / BB) * scale;
        logits[p] = lg;
        lmax = fmaxf(lmax, lg);
    }
    sm[t] = lmax; __syncthreads();
    for (int s = 128; s > 0; s >>= 1) {
        if (t < s) sm[t] = fmaxf(sm[t], sm[t + s]);
        __syncthreads();
    }
    float gmax = sm[0]; __syncthreads();

    float lsum = 0.f;
    for (int p = t; p < HWD; p += 256) {
        float e = expf(logits[p] - gmax);
        logits[p] = e;
        lsum += e;
    }
    sm[t] = lsum; __syncthreads();
    for (int s = 128; s > 0; s >>= 1) {
        if (t < s) sm[t] += sm[t + s];
        __syncthreads();
    }
    float inv = 1.0f / sm[0];
    for (int p = t; p < HWD; p += 256)
        g_w[b * HWD + p] = logits[p] * inv;
}

// ----------------------------------------------------------------------------
// Kernel 4: gated output conv, written directly in [B, C, HW] layout.
//   out[b,co,p] = w[b,p] * sum_ci W6[co,ci]*x[b,ci,p] + b6[co]
// ----------------------------------------------------------------------------
__global__ __launch_bounds__(256) void outconv_kernel(
    const float* __restrict__ x, const float* __restrict__ W6,
    const float* __restrict__ b6, float* __restrict__ out)
{
    __shared__ float As[16][128];   // As[kk][co] = W6[(co0+co), k0+kk]
    __shared__ float Bs[16][128];   // Bs[kk][p]  = x[b, k0+kk, p0+p]

    const int co0 = blockIdx.x * 128;
    const int p0  = blockIdx.y * 128;
    const int b   = blockIdx.z;
    const int t   = threadIdx.x;
    const int tx  = t & 15;
    const int ty  = t >> 4;

    float acc[8][8];
    #pragma unroll
    for (int i = 0; i < 8; i++)
        #pragma unroll
        for (int j = 0; j < 8; j++) acc[i][j] = 0.f;

    const float* xb = x + (size_t)b * CC * HWD;

    for (int k0 = 0; k0 < CC; k0 += 16) {
        #pragma unroll
        for (int u = 0; u < 2; u++) {
            int f  = t + u * 256;
            int co = f >> 2;
            int kq = (f & 3) << 2;
            float4 v = *(const float4*)(W6 + (size_t)(co0 + co) * CC + k0 + kq);
            As[kq + 0][co] = v.x; As[kq + 1][co] = v.y;
            As[kq + 2][co] = v.z; As[kq + 3][co] = v.w;
        }
        #pragma unroll
        for (int u = 0; u < 2; u++) {
            int f  = t + u * 256;
            int kk = f >> 5;
            int r4 = (f & 31) << 2;
            float4 v = *(const float4*)(xb + (size_t)(k0 + kk) * HWD + p0 + r4);
            *(float4*)(&Bs[kk][r4]) = v;
        }
        __syncthreads();
        #pragma unroll
        for (int kk = 0; kk < 16; kk++) {
            float a[8], bf[8];
            #pragma unroll
            for (int i = 0; i < 8; i++) a[i]  = As[kk][ty * 8 + i];
            #pragma unroll
            for (int j = 0; j < 8; j++) bf[j] = Bs[kk][tx * 8 + j];
            #pragma unroll
            for (int i = 0; i < 8; i++)
                #pragma unroll
                for (int j = 0; j < 8; j++)
                    acc[i][j] += a[i] * bf[j];
        }
        __syncthreads();
    }

    #pragma unroll
    for (int i = 0; i < 8; i++) {
        int co = co0 + ty * 8 + i;
        float bias = b6[co];
        #pragma unroll
        for (int j = 0; j < 8; j++) {
            int p = p0 + tx * 8 + j;
            out[((size_t)b * CC + co) * HWD + p] = acc[i][j] * g_w[b * HWD + p] + bias;
        }
    }
}

// ----------------------------------------------------------------------------
extern "C" void kernel_launch(void* const* d_in, const int* in_sizes, int n_in,
                              void* d_out, int out_size)
{
    const float* x  = (const float*)d_in[0];
    const float* Wq = (const float*)d_in[1];
    const float* bq = (const float*)d_in[2];
    const float* Wk = (const float*)d_in[3];
    const float* bk = (const float*)d_in[4];
    const float* W6 = (const float*)d_in[5];
    const float* b6 = (const float*)d_in[6];
    float* out = (float*)d_out;

    dim3 blk(256);
    proj_kernel<<<dim3(RR / 128, CC / 128), blk>>>(x, Wq, bq, 0);
    proj_kernel<<<dim3(RR / 128, CC / 128), blk>>>(x, Wk, bk, 1);
    scores_kernel<<<dim3(RR / 128, BB), blk>>>();
    softmax_kernel<<<BB, blk>>>();
    outconv_kernel<<<dim3(CC / 128, HWD / 128, BB), blk>>>(x, W6, b6, out);
}

// round 3
// speedup vs baseline: 2.6443x; 2.6443x over previous
#include <cuda_runtime.h>
#include <cstdint>

#define BB  8
#define CC  512
#define HWD 1024
#define RR  8192   // BB*HWD

// Scratch (device globals — no runtime allocation allowed)
__device__ float g_q[RR * CC];
__device__ float g_k[RR * CC];
__device__ float g_pmax[RR * BB];   // per-query, per-image max score
__device__ float g_w[BB * HWD];     // softmax gate weights

// ============================================================================
// Helpers
// ============================================================================
__device__ __forceinline__ uint32_t smem_u32(const void* p) {
    uint32_t a;
    asm("{ .reg .u64 t; cvta.to.shared.u64 t, %1; cvt.u32.u64 %0, t; }"
        : "=r"(a) : "l"(p));
    return a;
}
__device__ __forceinline__ void cp_cg16(uint32_t s, const void* g) {
    asm volatile("cp.async.cg.shared.global [%0], [%1], 16;" :: "r"(s), "l"(g));
}
__device__ __forceinline__ void cp_commit() {
    asm volatile("cp.async.commit_group;" ::: "memory");
}
template <int N> __device__ __forceinline__ void cp_wait() {
    asm volatile("cp.async.wait_group %0;" :: "n"(N) : "memory");
}
__device__ __forceinline__ void mma_tf32_16n8k8(
    float* c, uint32_t a0, uint32_t a1, uint32_t a2, uint32_t a3,
    uint32_t b0, uint32_t b1)
{
    asm volatile(
        "mma.sync.aligned.m16n8k8.row.col.f32.tf32.tf32.f32 "
        "{%0,%1,%2,%3}, {%4,%5,%6,%7}, {%8,%9}, {%0,%1,%2,%3};"
        : "+f"(c[0]), "+f"(c[1]), "+f"(c[2]), "+f"(c[3])
        : "r"(a0), "r"(a1), "r"(a2), "r"(a3), "r"(b0), "r"(b1));
}

// ============================================================================
// Kernel 1: q/k projection (one launch, grid.z selects q vs k). SIMT fp32.
// ============================================================================
__global__ __launch_bounds__(256) void proj_kernel(
    const float* __restrict__ x,
    const float* __restrict__ Wq, const float* __restrict__ bq,
    const float* __restrict__ Wk, const float* __restrict__ bk)
{
    const int dst = blockIdx.z;
    const float* W    = dst ? Wk : Wq;
    const float* bias = dst ? bk : bq;
    float* out        = dst ? g_k : g_q;

    __shared__ float As[16][128];
    __shared__ float Bs[16][128];

    const int r0  = blockIdx.x * 128;
    const int co0 = blockIdx.y * 128;
    const int b   = r0 / HWD;
    const int p0  = r0 % HWD;
    const int t   = threadIdx.x;
    const int tx  = t & 15;
    const int ty  = t >> 4;

    float acc[8][8];
    #pragma unroll
    for (int i = 0; i < 8; i++)
        #pragma unroll
        for (int j = 0; j < 8; j++) acc[i][j] = 0.f;

    const float* xb = x + (size_t)b * CC * HWD;

    for (int k0 = 0; k0 < CC; k0 += 16) {
        #pragma unroll
        for (int u = 0; u < 2; u++) {
            int f  = t + u * 256;
            int kk = f >> 5;
            int r4 = (f & 31) << 2;
            float4 v = *(const float4*)(xb + (size_t)(k0 + kk) * HWD + p0 + r4);
            *(float4*)(&As[kk][r4]) = v;
        }
        #pragma unroll
        for (int u = 0; u < 2; u++) {
            int f  = t + u * 256;
            int co = f >> 2;
            int kq = (f & 3) << 2;
            float4 v = *(const float4*)(W + (size_t)(co0 + co) * CC + k0 + kq);
            Bs[kq + 0][co] = v.x; Bs[kq + 1][co] = v.y;
            Bs[kq + 2][co] = v.z; Bs[kq + 3][co] = v.w;
        }
        __syncthreads();
        #pragma unroll
        for (int kk = 0; kk < 16; kk++) {
            float a[8], bf[8];
            #pragma unroll
            for (int i = 0; i < 8; i++) a[i]  = As[kk][ty * 8 + i];
            #pragma unroll
            for (int j = 0; j < 8; j++) bf[j] = Bs[kk][tx * 8 + j];
            #pragma unroll
            for (int i = 0; i < 8; i++)
                #pragma unroll
                for (int j = 0; j < 8; j++)
                    acc[i][j] += a[i] * bf[j];
        }
        __syncthreads();
    }

    #pragma unroll
    for (int i = 0; i < 8; i++) {
        int row = r0 + ty * 8 + i;
        #pragma unroll
        for (int j = 0; j < 8; j++) {
            int co = co0 + tx * 8 + j;
            out[(size_t)row * CC + co] = acc[i][j] + bias[co];
        }
    }
}

// ============================================================================
// Kernel 2: fused scores + per-image max via mma.sync tf32 (m16n8k8).
//   Block: 128 queries x 1024 keys (one image). 4 N-tiles of 256 keys;
//   K=512 in 32-float chunks, cp.async double-buffered. Warp grid 2x4,
//   warp tile 64x64. Per-N-tile epilogue: register row-max -> shfl ->
//   smem cross-warp reduce. Scores matrix never materialized.
// ============================================================================
#define SBK   32
#define SNT   256
#define APAD  36                       // 32 + 4 floats pad per row
#define A_F   (128 * APAD)             // floats per A buffer
#define B_F   (SNT * APAD)             // floats per B buffer
#define RED_OFF (2 * A_F + 2 * B_F)
#define SC_SMEM ((RED_OFF + 512) * 4)

__global__ __launch_bounds__(256, 1) void scores_mma_kernel()
{
    extern __shared__ float sm[];
    const uint32_t sbase = smem_u32(sm);

    const int t    = threadIdx.x;
    const int lane = t & 31;
    const int wid  = t >> 5;
    const int wm   = wid >> 2;          // 0..1  (M half)
    const int wn   = wid & 3;           // 0..3  (N quarter)
    const int gid  = lane >> 2;
    const int tig  = lane & 3;
    const int q0   = blockIdx.x * 128;
    const size_t kb = (size_t)blockIdx.y * HWD;

    float* red = sm + RED_OFF;          // [4][128]
    float qm = -1e30f;

    // per-thread cp.async coordinates
    const int ar[4] = { (t + 0) >> 3, (t + 256) >> 3, (t + 512) >> 3, (t + 768) >> 3 };
    const int ac    = (t & 7) * 4;

    const float* qp = g_q + (size_t)q0 * CC;

    for (int ntile = 0; ntile < 4; ++ntile) {
        const float* kp = g_k + (kb + (size_t)ntile * SNT) * CC;

        // ---- issue chunk 0 ----
        {
            uint32_t As = sbase;
            #pragma unroll
            for (int u = 0; u < 4; u++)
                cp_cg16(As + (uint32_t)(ar[u] * APAD + ac) * 4,
                        qp + (size_t)ar[u] * CC + ac);
            uint32_t Bs = sbase + (uint32_t)(2 * A_F) * 4;
            #pragma unroll
            for (int u = 0; u < 8; u++) {
                int f = t + u * 256, n = f >> 3;
                cp_cg16(Bs + (uint32_t)(n * APAD + ac) * 4,
                        kp + (size_t)n * CC + ac);
            }
            cp_commit();
        }

        float acc[4][8][4];
        #pragma unroll
        for (int mt = 0; mt < 4; mt++)
            #pragma unroll
            for (int nt = 0; nt < 8; nt++)
                #pragma unroll
                for (int v = 0; v < 4; v++) acc[mt][nt][v] = 0.f;

        for (int c = 0; c < 16; ++c) {
            if (c < 15) {
                const int buf = (c + 1) & 1;
                const int k0  = (c + 1) * SBK;
                uint32_t As = sbase + (uint32_t)(buf * A_F) * 4;
                #pragma unroll
                for (int u = 0; u < 4; u++)
                    cp_cg16(As + (uint32_t)(ar[u] * APAD + ac) * 4,
                            qp + (size_t)ar[u] * CC + k0 + ac);
                uint32_t Bs = sbase + (uint32_t)(2 * A_F + buf * B_F) * 4;
                #pragma unroll
                for (int u = 0; u < 8; u++) {
                    int f = t + u * 256, n = f >> 3;
                    cp_cg16(Bs + (uint32_t)(n * APAD + ac) * 4,
                            kp + (size_t)n * CC + k0 + ac);
                }
                cp_commit();
                cp_wait<1>();
            } else {
                cp_wait<0>();
            }
            __syncthreads();

            const float* Ab = sm + (c & 1) * A_F;
            const float* Bb = sm + 2 * A_F + (c & 1) * B_F;

            #pragma unroll
            for (int ks = 0; ks < 4; ++ks) {
                uint32_t a[4][4];
                #pragma unroll
                for (int mt = 0; mt < 4; ++mt) {
                    int r = wm * 64 + mt * 16 + gid;
                    int col = ks * 8 + tig;
                    a[mt][0] = __float_as_uint(Ab[r * APAD + col]);
                    a[mt][1] = __float_as_uint(Ab[(r + 8) * APAD + col]);
                    a[mt][2] = __float_as_uint(Ab[r * APAD + col + 4]);
                    a[mt][3] = __float_as_uint(Ab[(r + 8) * APAD + col + 4]);
                }
                #pragma unroll
                for (int nt = 0; nt < 8; ++nt) {
                    int n = wn * 64 + nt * 8 + gid;
                    int col = ks * 8 + tig;
                    uint32_t b0 = __float_as_uint(Bb[n * APAD + col]);
                    uint32_t b1 = __float_as_uint(Bb[n * APAD + col + 4]);
                    #pragma unroll
                    for (int mt = 0; mt < 4; ++mt)
                        mma_tf32_16n8k8(acc[mt][nt],
                                        a[mt][0], a[mt][1], a[mt][2], a[mt][3],
                                        b0, b1);
                }
            }
            __syncthreads();
        }

        // ---- epilogue: per-query max over this N-tile ----
        #pragma unroll
        for (int mt = 0; mt < 4; ++mt) {
            float m0 = -1e30f, m1 = -1e30f;
            #pragma unroll
            for (int nt = 0; nt < 8; ++nt) {
                m0 = fmaxf(m0, fmaxf(acc[mt][nt][0], acc[mt][nt][1]));
                m1 = fmaxf(m1, fmaxf(acc[mt][nt][2], acc[mt][nt][3]));
            }
            m0 = fmaxf(m0, __shfl_xor_sync(0xffffffffu, m0, 1));
            m0 = fmaxf(m0, __shfl_xor_sync(0xffffffffu, m0, 2));
            m1 = fmaxf(m1, __shfl_xor_sync(0xffffffffu, m1, 1));
            m1 = fmaxf(m1, __shfl_xor_sync(0xffffffffu, m1, 2));
            if (tig == 0) {
                int r = wm * 64 + mt * 16 + gid;
                red[wn * 128 + r]     = m0;
                red[wn * 128 + r + 8] = m1;
            }
        }
        __syncthreads();
        if (t < 128) {
            float v = fmaxf(fmaxf(red[t], red[128 + t]),
                            fmaxf(red[256 + t], red[384 + t]));
            qm = fmaxf(qm, v);
        }
        __syncthreads();
    }

    if (t < 128)
        g_pmax[(size_t)(q0 + t) * BB + blockIdx.y] = qm;
}

// ============================================================================
// Kernel 3: logits = mean-over-images(pmax) / sqrt(C); softmax per batch.
// ============================================================================
__global__ __launch_bounds__(256) void softmax_kernel()
{
    const int b = blockIdx.x;
    const int t = threadIdx.x;
    __shared__ float sm[256];
    __shared__ float logits[HWD];
    const float scale = 1.0f / sqrtf((float)CC);

    float lmax = -1e30f;
    for (int p = t; p < HWD; p += 256) {
        float s = 0.f;
        #pragma unroll
        for (int img = 0; img < BB; img++)
            s += g_pmax[(size_t)(b * HWD + p) * BB + img];
        float lg = s * (1.0f / BB) * scale;
        logits[p] = lg;
        lmax = fmaxf(lmax, lg);
    }
    sm[t] = lmax; __syncthreads();
    for (int s = 128; s > 0; s >>= 1) {
        if (t < s) sm[t] = fmaxf(sm[t], sm[t + s]);
        __syncthreads();
    }
    float gmax = sm[0]; __syncthreads();

    float lsum = 0.f;
    for (int p = t; p < HWD; p += 256) {
        float e = expf(logits[p] - gmax);
        logits[p] = e;
        lsum += e;
    }
    sm[t] = lsum; __syncthreads();
    for (int s = 128; s > 0; s >>= 1) {
        if (t < s) sm[t] += sm[t + s];
        __syncthreads();
    }
    float inv = 1.0f / sm[0];
    for (int p = t; p < HWD; p += 256)
        g_w[b * HWD + p] = logits[p] * inv;
}

// ============================================================================
// Kernel 4: gated output conv, written directly in [B, C, HW] layout.
// ============================================================================
__global__ __launch_bounds__(256) void outconv_kernel(
    const float* __restrict__ x, const float* __restrict__ W6,
    const float* __restrict__ b6, float* __restrict__ out)
{
    __shared__ float As[16][128];
    __shared__ float Bs[16][128];

    const int co0 = blockIdx.x * 128;
    const int p0  = blockIdx.y * 128;
    const int b   = blockIdx.z;
    const int t   = threadIdx.x;
    const int tx  = t & 15;
    const int ty  = t >> 4;

    float acc[8][8];
    #pragma unroll
    for (int i = 0; i < 8; i++)
        #pragma unroll
        for (int j = 0; j < 8; j++) acc[i][j] = 0.f;

    const float* xb = x + (size_t)b * CC * HWD;

    for (int k0 = 0; k0 < CC; k0 += 16) {
        #pragma unroll
        for (int u = 0; u < 2; u++) {
            int f  = t + u * 256;
            int co = f >> 2;
            int kq = (f & 3) << 2;
            float4 v = *(const float4*)(W6 + (size_t)(co0 + co) * CC + k0 + kq);
            As[kq + 0][co] = v.x; As[kq + 1][co] = v.y;
            As[kq + 2][co] = v.z; As[kq + 3][co] = v.w;
        }
        #pragma unroll
        for (int u = 0; u < 2; u++) {
            int f  = t + u * 256;
            int kk = f >> 5;
            int r4 = (f & 31) << 2;
            float4 v = *(const float4*)(xb + (size_t)(k0 + kk) * HWD + p0 + r4);
            *(float4*)(&Bs[kk][r4]) = v;
        }
        __syncthreads();
        #pragma unroll
        for (int kk = 0; kk < 16; kk++) {
            float a[8], bf[8];
            #pragma unroll
            for (int i = 0; i < 8; i++) a[i]  = As[kk][ty * 8 + i];
            #pragma unroll
            for (int j = 0; j < 8; j++) bf[j] = Bs[kk][tx * 8 + j];
            #pragma unroll
            for (int i = 0; i < 8; i++)
                #pragma unroll
                for (int j = 0; j < 8; j++)
                    acc[i][j] += a[i] * bf[j];
        }
        __syncthreads();
    }

    #pragma unroll
    for (int i = 0; i < 8; i++) {
        int co = co0 + ty * 8 + i;
        float bias = b6[co];
        #pragma unroll
        for (int j = 0; j < 8; j++) {
            int p = p0 + tx * 8 + j;
            out[((size_t)b * CC + co) * HWD + p] = acc[i][j] * g_w[b * HWD + p] + bias;
        }
    }
}

// ============================================================================
extern "C" void kernel_launch(void* const* d_in, const int* in_sizes, int n_in,
                              void* d_out, int out_size)
{
    const float* x  = (const float*)d_in[0];
    const float* Wq = (const float*)d_in[1];
    const float* bq = (const float*)d_in[2];
    const float* Wk = (const float*)d_in[3];
    const float* bk = (const float*)d_in[4];
    const float* W6 = (const float*)d_in[5];
    const float* b6 = (const float*)d_in[6];
    float* out = (float*)d_out;

    cudaFuncSetAttribute(scores_mma_kernel,
                         cudaFuncAttributeMaxDynamicSharedMemorySize, SC_SMEM);

    dim3 blk(256);
    proj_kernel<<<dim3(RR / 128, CC / 128, 2), blk>>>(x, Wq, bq, Wk, bk);
    scores_mma_kernel<<<dim3(RR / 128, BB), blk, SC_SMEM>>>();
    softmax_kernel<<<BB, blk>>>();
    outconv_kernel<<<dim3(CC / 128, HWD / 128, BB), blk>>>(x, W6, b6, out);
}

// round 4
// speedup vs baseline: 3.5904x; 1.3578x over previous
#include <cuda_runtime.h>
#include <cstdint>

#define BB  8
#define CC  512
#define HWD 1024
#define RR  8192   // BB*HWD

// Scratch (device globals — no runtime allocation allowed)
__device__ float g_q[RR * CC];
__device__ float g_k[RR * CC];
__device__ float g_pmax[RR * BB];   // per-query, per-image max score
__device__ float g_w[BB * HWD];     // softmax gate weights

// ============================================================================
// Helpers
// ============================================================================
__device__ __forceinline__ uint32_t smem_u32(const void* p) {
    uint32_t a;
    asm("{ .reg .u64 t; cvta.to.shared.u64 t, %1; cvt.u32.u64 %0, t; }"
        : "=r"(a) : "l"(p));
    return a;
}
__device__ __forceinline__ void cp_cg16(uint32_t s, const void* g) {
    asm volatile("cp.async.cg.shared.global [%0], [%1], 16;" :: "r"(s), "l"(g));
}
__device__ __forceinline__ void cp_commit() {
    asm volatile("cp.async.commit_group;" ::: "memory");
}
template <int N> __device__ __forceinline__ void cp_wait() {
    asm volatile("cp.async.wait_group %0;" :: "n"(N) : "memory");
}
__device__ __forceinline__ void mma_tf32_16n8k8(
    float* c, uint32_t a0, uint32_t a1, uint32_t a2, uint32_t a3,
    uint32_t b0, uint32_t b1)
{
    asm volatile(
        "mma.sync.aligned.m16n8k8.row.col.f32.tf32.tf32.f32 "
        "{%0,%1,%2,%3}, {%4,%5,%6,%7}, {%8,%9}, {%0,%1,%2,%3};"
        : "+f"(c[0]), "+f"(c[1]), "+f"(c[2]), "+f"(c[3])
        : "r"(a0), "r"(a1), "r"(a2), "r"(a3), "r"(b0), "r"(b1));
}
__device__ __forceinline__ void tf32_split(float v, uint32_t& hi, uint32_t& lo) {
    uint32_t hb = __float_as_uint(v) & 0xFFFFE000u;
    hi = hb;
    lo = __float_as_uint(v - __uint_as_float(hb));
}

// Shared tiling constants (all GEMM kernels: 256 threads, 8 warps)
#define SBK  32      // K-chunk (floats)
#define PADR 36      // pad for [rows][k] tiles (32+4)
#define PADK 136     // pad for [k][cols] tiles (128+8)

// ============================================================================
// Kernel 1: q/k projection on tf32 mma.sync. grid (64, 4, 2).
//   Block: 128 rows x 128 co, K=512 in 16 chunks, 3-stage cp.async ring.
//   A = xf tile stored [k][p] (PADK), B = W tile stored [co][k] (PADR).
// ============================================================================
#define PJ_A_F (SBK * PADK)          // 4352 floats / stage
#define PJ_B_F (128 * PADR)          // 4608 floats / stage
#define PJ_SMEM (3 * (PJ_A_F + PJ_B_F) * 4)

__global__ __launch_bounds__(256) void proj_tc_kernel(
    const float* __restrict__ x,
    const float* __restrict__ Wq, const float* __restrict__ bq,
    const float* __restrict__ Wk, const float* __restrict__ bk)
{
    extern __shared__ float sm[];
    const uint32_t sbase = smem_u32(sm);

    const int dst = blockIdx.z;
    const float* W    = dst ? Wk : Wq;
    const float* bias = dst ? bk : bq;
    float* out        = dst ? g_k : g_q;

    const int t    = threadIdx.x;
    const int lane = t & 31;
    const int wid  = t >> 5;
    const int wm   = wid >> 2;         // 0..1
    const int wn   = wid & 3;          // 0..3
    const int gid  = lane >> 2;
    const int tig  = lane & 3;

    const int r0  = blockIdx.x * 128;
    const int co0 = blockIdx.y * 128;
    const int b   = r0 / HWD;
    const int p0  = r0 % HWD;
    const float* xb = x + (size_t)b * CC * HWD;

    auto issue = [&](int c) {
        const int s  = c % 3;
        const int k0 = c * SBK;
        uint32_t As = sbase + (uint32_t)(s * PJ_A_F) * 4;
        #pragma unroll
        for (int u = 0; u < 4; u++) {
            int f = t + u * 256, kk = f >> 5, p4 = (f & 31) * 4;
            cp_cg16(As + (uint32_t)(kk * PADK + p4) * 4,
                    xb + (size_t)(k0 + kk) * HWD + p0 + p4);
        }
        uint32_t Bs = sbase + (uint32_t)(3 * PJ_A_F + s * PJ_B_F) * 4;
        #pragma unroll
        for (int u = 0; u < 4; u++) {
            int f = t + u * 256, n = f >> 3, c4 = (f & 7) * 4;
            cp_cg16(Bs + (uint32_t)(n * PADR + c4) * 4,
                    W + (size_t)(co0 + n) * CC + k0 + c4);
        }
        cp_commit();
    };

    float acc[4][4][4];
    #pragma unroll
    for (int mt = 0; mt < 4; mt++)
        #pragma unroll
        for (int nt = 0; nt < 4; nt++)
            #pragma unroll
            for (int v = 0; v < 4; v++) acc[mt][nt][v] = 0.f;

    issue(0); issue(1);
    for (int c = 0; c < 16; ++c) {
        if (c < 15) cp_wait<1>(); else cp_wait<0>();
        __syncthreads();
        if (c + 2 < 16) issue(c + 2);

        const float* Ab = sm + (c % 3) * PJ_A_F;                 // [k][p]
        const float* Bb = sm + 3 * PJ_A_F + (c % 3) * PJ_B_F;    // [co][k]

        #pragma unroll
        for (int ks = 0; ks < 4; ++ks) {
            const int col = ks * 8 + tig;
            uint32_t a[4][4];
            #pragma unroll
            for (int mt = 0; mt < 4; ++mt) {
                int r = wm * 64 + mt * 16 + gid;
                a[mt][0] = __float_as_uint(Ab[col * PADK + r]);
                a[mt][1] = __float_as_uint(Ab[col * PADK + r + 8]);
                a[mt][2] = __float_as_uint(Ab[(col + 4) * PADK + r]);
                a[mt][3] = __float_as_uint(Ab[(col + 4) * PADK + r + 8]);
            }
            #pragma unroll
            for (int nt = 0; nt < 4; ++nt) {
                int n = wn * 32 + nt * 8 + gid;
                uint32_t b0 = __float_as_uint(Bb[n * PADR + col]);
                uint32_t b1 = __float_as_uint(Bb[n * PADR + col + 4]);
                #pragma unroll
                for (int mt = 0; mt < 4; ++mt)
                    mma_tf32_16n8k8(acc[mt][nt],
                                    a[mt][0], a[mt][1], a[mt][2], a[mt][3],
                                    b0, b1);
            }
        }
    }

    #pragma unroll
    for (int mt = 0; mt < 4; ++mt) {
        int row = r0 + wm * 64 + mt * 16 + gid;
        #pragma unroll
        for (int nt = 0; nt < 4; ++nt) {
            int co = co0 + wn * 32 + nt * 8 + tig * 2;
            float bs0 = bias[co], bs1 = bias[co + 1];
            float2 o0 = { acc[mt][nt][0] + bs0, acc[mt][nt][1] + bs1 };
            float2 o1 = { acc[mt][nt][2] + bs0, acc[mt][nt][3] + bs1 };
            *(float2*)&out[(size_t)row * CC + co]       = o0;
            *(float2*)&out[(size_t)(row + 8) * CC + co] = o1;
        }
    }
}

// ============================================================================
// Kernel 2: fused scores + per-image max via tf32 mma. grid (64, 8).
//   Block: 128 queries x 1024 keys (one image). Flattened 64-chunk loop
//   (4 N-tiles x 16 K-chunks), 3-stage cp.async ring, 1 sync per chunk.
// ============================================================================
#define SNT   256
#define SC_A_F (128 * PADR)          // 4608
#define SC_B_F (SNT * PADR)          // 9216
#define SC_RED (3 * (SC_A_F + SC_B_F))
#define SC_SMEM ((SC_RED + 512) * 4)

__global__ __launch_bounds__(256, 1) void scores_mma_kernel()
{
    extern __shared__ float sm[];
    const uint32_t sbase = smem_u32(sm);

    const int t    = threadIdx.x;
    const int lane = t & 31;
    const int wid  = t >> 5;
    const int wm   = wid >> 2;
    const int wn   = wid & 3;
    const int gid  = lane >> 2;
    const int tig  = lane & 3;
    const int q0   = blockIdx.x * 128;
    const size_t kb = (size_t)blockIdx.y * HWD;

    float* red = sm + SC_RED;
    float qm = -1e30f;
    const float* qp = g_q + (size_t)q0 * CC;

    auto issue = [&](int g) {
        const int s   = g % 3;
        const int ntl = g >> 4;
        const int k0  = (g & 15) * SBK;
        uint32_t As = sbase + (uint32_t)(s * SC_A_F) * 4;
        #pragma unroll
        for (int u = 0; u < 4; u++) {
            int f = t + u * 256, r = f >> 3, c4 = (f & 7) * 4;
            cp_cg16(As + (uint32_t)(r * PADR + c4) * 4,
                    qp + (size_t)r * CC + k0 + c4);
        }
        uint32_t Bs = sbase + (uint32_t)(3 * SC_A_F + s * SC_B_F) * 4;
        const float* kp = g_k + (kb + (size_t)ntl * SNT) * CC;
        #pragma unroll
        for (int u = 0; u < 8; u++) {
            int f = t + u * 256, n = f >> 3, c4 = (f & 7) * 4;
            cp_cg16(Bs + (uint32_t)(n * PADR + c4) * 4,
                    kp + (size_t)n * CC + k0 + c4);
        }
        cp_commit();
    };

    float acc[4][8][4];

    issue(0); issue(1);
    for (int g = 0; g < 64; ++g) {
        if ((g & 15) == 0) {
            #pragma unroll
            for (int mt = 0; mt < 4; mt++)
                #pragma unroll
                for (int nt = 0; nt < 8; nt++)
                    #pragma unroll
                    for (int v = 0; v < 4; v++) acc[mt][nt][v] = 0.f;
        }
        if (g < 63) cp_wait<1>(); else cp_wait<0>();
        __syncthreads();
        if (g + 2 < 64) issue(g + 2);

        const float* Ab = sm + (g % 3) * SC_A_F;                 // [r][k]
        const float* Bb = sm + 3 * SC_A_F + (g % 3) * SC_B_F;    // [n][k]

        #pragma unroll
        for (int ks = 0; ks < 4; ++ks) {
            const int col = ks * 8 + tig;
            uint32_t a[4][4];
            #pragma unroll
            for (int mt = 0; mt < 4; ++mt) {
                int r = wm * 64 + mt * 16 + gid;
                a[mt][0] = __float_as_uint(Ab[r * PADR + col]);
                a[mt][1] = __float_as_uint(Ab[(r + 8) * PADR + col]);
                a[mt][2] = __float_as_uint(Ab[r * PADR + col + 4]);
                a[mt][3] = __float_as_uint(Ab[(r + 8) * PADR + col + 4]);
            }
            #pragma unroll
            for (int nt = 0; nt < 8; ++nt) {
                int n = wn * 64 + nt * 8 + gid;
                uint32_t b0 = __float_as_uint(Bb[n * PADR + col]);
                uint32_t b1 = __float_as_uint(Bb[n * PADR + col + 4]);
                #pragma unroll
                for (int mt = 0; mt < 4; ++mt)
                    mma_tf32_16n8k8(acc[mt][nt],
                                    a[mt][0], a[mt][1], a[mt][2], a[mt][3],
                                    b0, b1);
            }
        }

        if ((g & 15) == 15) {
            #pragma unroll
            for (int mt = 0; mt < 4; ++mt) {
                float m0 = -1e30f, m1 = -1e30f;
                #pragma unroll
                for (int nt = 0; nt < 8; ++nt) {
                    m0 = fmaxf(m0, fmaxf(acc[mt][nt][0], acc[mt][nt][1]));
                    m1 = fmaxf(m1, fmaxf(acc[mt][nt][2], acc[mt][nt][3]));
                }
                m0 = fmaxf(m0, __shfl_xor_sync(0xffffffffu, m0, 1));
                m0 = fmaxf(m0, __shfl_xor_sync(0xffffffffu, m0, 2));
                m1 = fmaxf(m1, __shfl_xor_sync(0xffffffffu, m1, 1));
                m1 = fmaxf(m1, __shfl_xor_sync(0xffffffffu, m1, 2));
                if (tig == 0) {
                    int r = wm * 64 + mt * 16 + gid;
                    red[wn * 128 + r]     = m0;
                    red[wn * 128 + r + 8] = m1;
                }
            }
            __syncthreads();
            if (t < 128) {
                float v = fmaxf(fmaxf(red[t], red[128 + t]),
                                fmaxf(red[256 + t], red[384 + t]));
                qm = fmaxf(qm, v);
            }
            __syncthreads();
        }
    }

    if (t < 128)
        g_pmax[(size_t)(q0 + t) * BB + blockIdx.y] = qm;
}

// ============================================================================
// Kernel 3: logits = mean-over-images(pmax) / sqrt(C); softmax per batch.
// ============================================================================
__global__ __launch_bounds__(256) void softmax_kernel()
{
    const int b = blockIdx.x;
    const int t = threadIdx.x;
    __shared__ float smr[256];
    __shared__ float logits[HWD];
    const float scale = 1.0f / sqrtf((float)CC);

    float lmax = -1e30f;
    for (int p = t; p < HWD; p += 256) {
        float s = 0.f;
        #pragma unroll
        for (int img = 0; img < BB; img++)
            s += g_pmax[(size_t)(b * HWD + p) * BB + img];
        float lg = s * (1.0f / BB) * scale;
        logits[p] = lg;
        lmax = fmaxf(lmax, lg);
    }
    smr[t] = lmax; __syncthreads();
    for (int s = 128; s > 0; s >>= 1) {
        if (t < s) smr[t] = fmaxf(smr[t], smr[t + s]);
        __syncthreads();
    }
    float gmax = smr[0]; __syncthreads();

    float lsum = 0.f;
    for (int p = t; p < HWD; p += 256) {
        float e = expf(logits[p] - gmax);
        logits[p] = e;
        lsum += e;
    }
    smr[t] = lsum; __syncthreads();
    for (int s = 128; s > 0; s >>= 1) {
        if (t < s) smr[t] += smr[t + s];
        __syncthreads();
    }
    float inv = 1.0f / smr[0];
    for (int p = t; p < HWD; p += 256)
        g_w[b * HWD + p] = logits[p] * inv;
}

// ============================================================================
// Kernel 4: gated output conv on 3xTF32 split mma. grid (4, 8, 8).
//   out[b,co,p] = gate[b,p] * (W6 @ x_b)[co,p] + b6[co]
//   A = W6 [co][k] (PADR), B = x tile [k][p] (PADK). Error ~2^-19.
// ============================================================================
__global__ __launch_bounds__(256) void outconv_tc_kernel(
    const float* __restrict__ x, const float* __restrict__ W6,
    const float* __restrict__ b6, float* __restrict__ out)
{
    extern __shared__ float sm[];
    const uint32_t sbase = smem_u32(sm);

    const int t    = threadIdx.x;
    const int lane = t & 31;
    const int wid  = t >> 5;
    const int wm   = wid >> 2;
    const int wn   = wid & 3;
    const int gid  = lane >> 2;
    const int tig  = lane & 3;

    const int co0 = blockIdx.x * 128;
    const int p0  = blockIdx.y * 128;
    const int b   = blockIdx.z;
    const float* xb = x + (size_t)b * CC * HWD;

    auto issue = [&](int c) {
        const int s  = c % 3;
        const int k0 = c * SBK;
        uint32_t As = sbase + (uint32_t)(s * PJ_B_F) * 4;      // [co][k] PADR
        #pragma unroll
        for (int u = 0; u < 4; u++) {
            int f = t + u * 256, m = f >> 3, c4 = (f & 7) * 4;
            cp_cg16(As + (uint32_t)(m * PADR + c4) * 4,
                    W6 + (size_t)(co0 + m) * CC + k0 + c4);
        }
        uint32_t Bs = sbase + (uint32_t)(3 * PJ_B_F + s * PJ_A_F) * 4;  // [k][p] PADK
        #pragma unroll
        for (int u = 0; u < 4; u++) {
            int f = t + u * 256, kk = f >> 5, p4 = (f & 31) * 4;
            cp_cg16(Bs + (uint32_t)(kk * PADK + p4) * 4,
                    xb + (size_t)(k0 + kk) * HWD + p0 + p4);
        }
        cp_commit();
    };

    float acc[4][4][4];
    #pragma unroll
    for (int mt = 0; mt < 4; mt++)
        #pragma unroll
        for (int nt = 0; nt < 4; nt++)
            #pragma unroll
            for (int v = 0; v < 4; v++) acc[mt][nt][v] = 0.f;

    issue(0); issue(1);
    for (int c = 0; c < 16; ++c) {
        if (c < 15) cp_wait<1>(); else cp_wait<0>();
        __syncthreads();
        if (c + 2 < 16) issue(c + 2);

        const float* Ab = sm + (c % 3) * PJ_B_F;                 // [co][k]
        const float* Bb = sm + 3 * PJ_B_F + (c % 3) * PJ_A_F;    // [k][p]

        #pragma unroll
        for (int ks = 0; ks < 4; ++ks) {
            const int col = ks * 8 + tig;
            uint32_t ah[4][4], al[4][4];
            #pragma unroll
            for (int mt = 0; mt < 4; ++mt) {
                int m = wm * 64 + mt * 16 + gid;
                tf32_split(Ab[m * PADR + col],           ah[mt][0], al[mt][0]);
                tf32_split(Ab[(m + 8) * PADR + col],     ah[mt][1], al[mt][1]);
                tf32_split(Ab[m * PADR + col + 4],       ah[mt][2], al[mt][2]);
                tf32_split(Ab[(m + 8) * PADR + col + 4], ah[mt][3], al[mt][3]);
            }
            #pragma unroll
            for (int nt = 0; nt < 4; ++nt) {
                int n = wn * 32 + nt * 8 + gid;
                uint32_t bh0, bl0, bh1, bl1;
                tf32_split(Bb[col * PADK + n],       bh0, bl0);
                tf32_split(Bb[(col + 4) * PADK + n], bh1, bl1);
                #pragma unroll
                for (int mt = 0; mt < 4; ++mt) {
                    mma_tf32_16n8k8(acc[mt][nt],
                                    ah[mt][0], ah[mt][1], ah[mt][2], ah[mt][3],
                                    bh0, bh1);
                    mma_tf32_16n8k8(acc[mt][nt],
                                    ah[mt][0], ah[mt][1], ah[mt][2], ah[mt][3],
                                    bl0, bl1);
                    mma_tf32_16n8k8(acc[mt][nt],
                                    al[mt][0], al[mt][1], al[mt][2], al[mt][3],
                                    bh0, bh1);
                }
            }
        }
    }

    #pragma unroll
    for (int mt = 0; mt < 4; ++mt) {
        int co = co0 + wm * 64 + mt * 16 + gid;
        float bs0 = b6[co], bs1 = b6[co + 8];
        #pragma unroll
        for (int nt = 0; nt < 4; ++nt) {
            int p = p0 + wn * 32 + nt * 8 + tig * 2;
            float g0 = g_w[b * HWD + p];
            float g1 = g_w[b * HWD + p + 1];
            float2 o0 = { acc[mt][nt][0] * g0 + bs0, acc[mt][nt][1] * g1 + bs0 };
            float2 o1 = { acc[mt][nt][2] * g0 + bs1, acc[mt][nt][3] * g1 + bs1 };
            *(float2*)&out[((size_t)(b * CC + co)) * HWD + p]     = o0;
            *(float2*)&out[((size_t)(b * CC + co + 8)) * HWD + p] = o1;
        }
    }
}

// ============================================================================
extern "C" void kernel_launch(void* const* d_in, const int* in_sizes, int n_in,
                              void* d_out, int out_size)
{
    const float* x  = (const float*)d_in[0];
    const float* Wq = (const float*)d_in[1];
    const float* bq = (const float*)d_in[2];
    const float* Wk = (const float*)d_in[3];
    const float* bk = (const float*)d_in[4];
    const float* W6 = (const float*)d_in[5];
    const float* b6 = (const float*)d_in[6];
    float* out = (float*)d_out;

    cudaFuncSetAttribute(proj_tc_kernel,
                         cudaFuncAttributeMaxDynamicSharedMemorySize, PJ_SMEM);
    cudaFuncSetAttribute(scores_mma_kernel,
                         cudaFuncAttributeMaxDynamicSharedMemorySize, SC_SMEM);
    cudaFuncSetAttribute(outconv_tc_kernel,
                         cudaFuncAttributeMaxDynamicSharedMemorySize, PJ_SMEM);

    dim3 blk(256);
    proj_tc_kernel<<<dim3(RR / 128, CC / 128, 2), blk, PJ_SMEM>>>(x, Wq, bq, Wk, bk);
    scores_mma_kernel<<<dim3(RR / 128, BB), blk, SC_SMEM>>>();
    softmax_kernel<<<BB, blk>>>();
    outconv_tc_kernel<<<dim3(CC / 128, HWD / 128, BB), blk, PJ_SMEM>>>(x, W6, b6, out);
}